// round 11
// baseline (speedup 1.0000x reference)
#include <cuda_runtime.h>

#define BB 4
#define CC 64
#define HH 512
#define WW 512
#define HWSZ (HH * WW)            // 262144
#define NPIX (BB * HWSZ)          // 1048576
#define NQUAD (NPIX / 4)          // 262144
#define N_ORI 20
#define NBLOCKS (NQUAD / 256)     // 1024
#define STAGES 6                  // 16B/thread per stage, 24 KB ring
#define IGN 255

// Scratch (allocation-free per harness rules). Statically zeroed for first
// run; the last block of each run resets them, keeping graph replays
// deterministic.
__device__ double g_sum = 0.0;
__device__ unsigned long long g_cnt = 0ull;
__device__ unsigned int g_ticket = 0u;

__device__ __forceinline__ void cp_async16(unsigned int saddr, const void* gptr) {
    asm volatile("cp.async.cg.shared.global [%0], [%1], 16;\n"
                 :: "r"(saddr), "l"(gptr) : "memory");
}
__device__ __forceinline__ void cp_commit() {
    asm volatile("cp.async.commit_group;\n" ::: "memory");
}
template <int N>
__device__ __forceinline__ void cp_wait() {
    asm volatile("cp.async.wait_group %0;\n" :: "n"(N) : "memory");
}

__global__ __launch_bounds__(256, 7) void uce_kernel(
    const float* __restrict__ inp,   // [B, C, H, W] f32
    const int* __restrict__ tgt,     // [B, H, W] int32
    const int* __restrict__ gid,     // [C] int32
    float* __restrict__ out)
{
    __shared__ __align__(16) float4 sbuf[STAGES * 256];   // 24 KB ring
    __shared__ int sgid[CC];

    int tid = threadIdx.x;
    if (tid < CC) sgid[tid] = gid[tid];
    __syncthreads();

    int q = blockIdx.x * 256 + tid;          // quad index (4 pixels/thread)
    int p  = q << 2;
    int b  = p >> 18;                        // p / HWSZ
    int hw = p & (HWSZ - 1);                 // multiple of 4 -> float4 aligned
    const float* base = inp + (size_t)b * (CC * HWSZ) + hw;

    int4 t = *reinterpret_cast<const int4*>(tgt + p);   // overlap with prologue

    // This thread's slot in stage 0 (stage s = +s*4096 bytes)
    unsigned int slot0 = (unsigned int)__cvta_generic_to_shared(&sbuf[tid]);

    // Prologue: fill all stages (channels 0..STAGES-1)
    #pragma unroll
    for (int s = 0; s < STAGES; ++s) {
        cp_async16(slot0 + s * 4096, base + (size_t)s * HWSZ);
        cp_commit();
    }

    float a0 = 0.f, a1 = 0.f, a2 = 0.f, a3 = 0.f;   // all-channel sums
    float s0 = 0.f, s1 = 0.f, s2 = 0.f, s3 = 0.f;   // target-group sums

    int slot = 0;
    #pragma unroll 6
    for (int c = 0; c < CC; ++c) {
        cp_wait<STAGES - 1>();                       // oldest stage (channel c) ready
        float4 v = sbuf[slot * 256 + tid];           // self-consume, no barrier
        int g = sgid[c];                             // broadcast LDS

        float e0 = __expf(v.x), e1 = __expf(v.y);
        float e2 = __expf(v.z), e3 = __expf(v.w);
        a0 += e0; a1 += e1; a2 += e2; a3 += e3;
        if (g == t.x) s0 += e0;
        if (g == t.y) s1 += e1;
        if (g == t.z) s2 += e2;
        if (g == t.w) s3 += e3;

        int nc = c + STAGES;
        if (nc < CC)
            cp_async16(slot0 + slot * 4096, base + (size_t)nc * HWSZ);
        cp_commit();                                 // empty tail groups are fine
        slot = (slot == STAGES - 1) ? 0 : slot + 1;
    }

    // Targets outside [0, N_ORI) (incl. ignore=255) never matched -> s stays 0.
    bool v0 = (unsigned)t.x < N_ORI;
    bool v1 = (unsigned)t.y < N_ORI;
    bool v2 = (unsigned)t.z < N_ORI;
    bool v3 = (unsigned)t.w < N_ORI;

    float lsum = 0.0f;
    int   lcnt = 0;
    // -(log(s_t) - log(s_all)) = log(s_all) - log(s_t)
    if (v0) { lsum += __logf(a0) - __logf(s0); lcnt++; }
    if (v1) { lsum += __logf(a1) - __logf(s1); lcnt++; }
    if (v2) { lsum += __logf(a2) - __logf(s2); lcnt++; }
    if (v3) { lsum += __logf(a3) - __logf(s3); lcnt++; }

    // Warp reduce
    #pragma unroll
    for (int o = 16; o > 0; o >>= 1) {
        lsum += __shfl_down_sync(0xFFFFFFFFu, lsum, o);
        lcnt += __shfl_down_sync(0xFFFFFFFFu, lcnt, o);
    }

    __shared__ float wsum[8];
    __shared__ int   wcnt[8];
    int wid = tid >> 5;
    int lid = tid & 31;
    if (lid == 0) { wsum[wid] = lsum; wcnt[wid] = lcnt; }
    __syncthreads();

    __shared__ bool s_last;
    if (tid == 0) {
        float bs = 0.f; int bc = 0;
        #pragma unroll
        for (int w = 0; w < 8; ++w) { bs += wsum[w]; bc += wcnt[w]; }
        atomicAdd(&g_sum, (double)bs);
        atomicAdd(&g_cnt, (unsigned long long)bc);
        __threadfence();
        unsigned int ticket = atomicAdd(&g_ticket, 1u);
        s_last = (ticket == NBLOCKS - 1);
    }
    __syncthreads();

    if (s_last && tid == 0) {
        double sum = atomicAdd(&g_sum, 0.0);                    // acquire-read
        unsigned long long n = atomicAdd(&g_cnt, 0ull);
        if (n < 1ull) n = 1ull;
        out[0] = (float)(sum / (double)n);
        // Reset scratch for the next graph replay (deterministic).
        g_sum = 0.0;
        g_cnt = 0ull;
        __threadfence();
        g_ticket = 0u;
    }
}

extern "C" void kernel_launch(void* const* d_in, const int* in_sizes, int n_in,
                              void* d_out, int out_size) {
    const float* inp = (const float*)d_in[0];
    const int*   tgt = (const int*)d_in[1];
    const int*   gid = (const int*)d_in[2];
    float*       out = (float*)d_out;

    uce_kernel<<<NBLOCKS, 256>>>(inp, tgt, gid, out);
}

// round 12
// speedup vs baseline: 1.0189x; 1.0189x over previous
#include <cuda_runtime.h>

#define BB 4
#define CC 64
#define HH 512
#define WW 512
#define HWSZ (HH * WW)            // 262144
#define NPIX (BB * HWSZ)          // 1048576
#define NQUAD (NPIX / 4)          // 262144
#define NTHR 128
#define NBLOCKS (NQUAD / NTHR)    // 2048
#define N_ORI 20
#define STAGES 4                  // 16B/thread per stage, 8 KB ring
#define IGN 255

// Scratch (allocation-free per harness rules). Statically zeroed for first
// run; the last block of each run resets them, keeping graph replays
// deterministic.
__device__ double g_sum = 0.0;
__device__ unsigned long long g_cnt = 0ull;
__device__ unsigned int g_ticket = 0u;

__device__ __forceinline__ void cp_async16(unsigned int saddr, const void* gptr) {
    asm volatile("cp.async.cg.shared.global [%0], [%1], 16;\n"
                 :: "r"(saddr), "l"(gptr) : "memory");
}
__device__ __forceinline__ void cp_commit() {
    asm volatile("cp.async.commit_group;\n" ::: "memory");
}
template <int N>
__device__ __forceinline__ void cp_wait() {
    asm volatile("cp.async.wait_group %0;\n" :: "n"(N) : "memory");
}

__global__ __launch_bounds__(NTHR, 14) void uce_kernel(
    const float* __restrict__ inp,   // [B, C, H, W] f32
    const int* __restrict__ tgt,     // [B, H, W] int32
    const int* __restrict__ gid,     // [C] int32
    float* __restrict__ out)
{
    __shared__ __align__(16) float4 sbuf[STAGES * NTHR];   // 8 KB ring
    __shared__ int sgid[CC];

    int tid = threadIdx.x;
    if (tid < CC) sgid[tid] = gid[tid];
    __syncthreads();

    int q = blockIdx.x * NTHR + tid;         // quad index (4 pixels/thread)
    int p  = q << 2;
    int b  = p >> 18;                        // p / HWSZ
    int hw = p & (HWSZ - 1);                 // multiple of 4 -> float4 aligned
    const float* base = inp + (size_t)b * (CC * HWSZ) + hw;

    int4 t = *reinterpret_cast<const int4*>(tgt + p);   // overlap with prologue

    // This thread's slot in stage 0 (stage s = +s*2048 bytes)
    unsigned int slot0 = (unsigned int)__cvta_generic_to_shared(&sbuf[tid]);

    // Prologue: fill all stages (channels 0..STAGES-1)
    #pragma unroll
    for (int s = 0; s < STAGES; ++s) {
        cp_async16(slot0 + s * (NTHR * 16), base + (size_t)s * HWSZ);
        cp_commit();
    }

    float a0 = 0.f, a1 = 0.f, a2 = 0.f, a3 = 0.f;   // all-channel sums
    float s0 = 0.f, s1 = 0.f, s2 = 0.f, s3 = 0.f;   // target-group sums

    #pragma unroll 8
    for (int c = 0; c < CC; ++c) {
        cp_wait<STAGES - 1>();                       // oldest stage (channel c) ready
        int slot = (c & (STAGES - 1));               // compile-time under unroll 8
        float4 v = sbuf[slot * NTHR + tid];          // self-consume, no barrier
        int g = sgid[c];                             // broadcast LDS

        float e0 = __expf(v.x), e1 = __expf(v.y);
        float e2 = __expf(v.z), e3 = __expf(v.w);
        a0 += e0; a1 += e1; a2 += e2; a3 += e3;
        if (g == t.x) s0 += e0;
        if (g == t.y) s1 += e1;
        if (g == t.z) s2 += e2;
        if (g == t.w) s3 += e3;

        int nc = c + STAGES;
        if (nc < CC)
            cp_async16(slot0 + slot * (NTHR * 16), base + (size_t)nc * HWSZ);
        cp_commit();                                 // empty tail groups are fine
    }

    // Targets outside [0, N_ORI) (incl. ignore=255) never matched -> s stays 0.
    bool v0 = (unsigned)t.x < N_ORI;
    bool v1 = (unsigned)t.y < N_ORI;
    bool v2 = (unsigned)t.z < N_ORI;
    bool v3 = (unsigned)t.w < N_ORI;

    float lsum = 0.0f;
    int   lcnt = 0;
    // -(log(s_t) - log(s_all)) = log(s_all) - log(s_t)
    if (v0) { lsum += __logf(a0) - __logf(s0); lcnt++; }
    if (v1) { lsum += __logf(a1) - __logf(s1); lcnt++; }
    if (v2) { lsum += __logf(a2) - __logf(s2); lcnt++; }
    if (v3) { lsum += __logf(a3) - __logf(s3); lcnt++; }

    // Warp reduce
    #pragma unroll
    for (int o = 16; o > 0; o >>= 1) {
        lsum += __shfl_down_sync(0xFFFFFFFFu, lsum, o);
        lcnt += __shfl_down_sync(0xFFFFFFFFu, lcnt, o);
    }

    __shared__ float wsum[4];
    __shared__ int   wcnt[4];
    int wid = tid >> 5;
    int lid = tid & 31;
    if (lid == 0) { wsum[wid] = lsum; wcnt[wid] = lcnt; }
    __syncthreads();

    __shared__ bool s_last;
    if (tid == 0) {
        float bs = 0.f; int bc = 0;
        #pragma unroll
        for (int w = 0; w < 4; ++w) { bs += wsum[w]; bc += wcnt[w]; }
        atomicAdd(&g_sum, (double)bs);
        atomicAdd(&g_cnt, (unsigned long long)bc);
        __threadfence();
        unsigned int ticket = atomicAdd(&g_ticket, 1u);
        s_last = (ticket == NBLOCKS - 1);
    }
    __syncthreads();

    if (s_last && tid == 0) {
        double sum = atomicAdd(&g_sum, 0.0);                    // acquire-read
        unsigned long long n = atomicAdd(&g_cnt, 0ull);
        if (n < 1ull) n = 1ull;
        out[0] = (float)(sum / (double)n);
        // Reset scratch for the next graph replay (deterministic).
        g_sum = 0.0;
        g_cnt = 0ull;
        __threadfence();
        g_ticket = 0u;
    }
}

extern "C" void kernel_launch(void* const* d_in, const int* in_sizes, int n_in,
                              void* d_out, int out_size) {
    const float* inp = (const float*)d_in[0];
    const int*   tgt = (const int*)d_in[1];
    const int*   gid = (const int*)d_in[2];
    float*       out = (float*)d_out;

    uce_kernel<<<NBLOCKS, NTHR>>>(inp, tgt, gid, out);
}

// round 14
// speedup vs baseline: 1.0510x; 1.0315x over previous
#include <cuda_runtime.h>

#define BB 4
#define CC 64
#define HH 512
#define WW 512
#define HWSZ (HH * WW)            // 262144
#define NPIX (BB * HWSZ)          // 1048576
#define NQUAD (NPIX / 4)          // 262144
#define N_ORI 20
#define NBLOCKS (NQUAD / 256)     // 1024
#define STAGES 4                  // 16B/thread per stage, 16 KB ring
#define IGN 255

// Scratch (allocation-free per harness rules). Statically zeroed for first
// run; the last block of each run resets them, keeping graph replays
// deterministic.
__device__ double g_sum = 0.0;
__device__ unsigned long long g_cnt = 0ull;
__device__ unsigned int g_ticket = 0u;

__device__ __forceinline__ void cp_async16(unsigned int saddr, const void* gptr) {
    asm volatile("cp.async.cg.shared.global [%0], [%1], 16;\n"
                 :: "r"(saddr), "l"(gptr) : "memory");
}
__device__ __forceinline__ void cp_commit() {
    asm volatile("cp.async.commit_group;\n" ::: "memory");
}
template <int N>
__device__ __forceinline__ void cp_wait() {
    asm volatile("cp.async.wait_group %0;\n" :: "n"(N) : "memory");
}

__global__ __launch_bounds__(256, 7) void uce_kernel(
    const float* __restrict__ inp,   // [B, C, H, W] f32
    const int* __restrict__ tgt,     // [B, H, W] int32
    const int* __restrict__ gid,     // [C] int32
    float* __restrict__ out)
{
    __shared__ __align__(16) float4 sbuf[STAGES * 256];   // 16 KB ring
    __shared__ int sgid[CC];

    int tid = threadIdx.x;
    if (tid < CC) sgid[tid] = gid[tid];
    __syncthreads();

    int q = blockIdx.x * 256 + tid;          // quad index (4 pixels/thread)
    int p  = q << 2;
    int b  = p >> 18;                        // p / HWSZ
    int hw = p & (HWSZ - 1);                 // multiple of 4 -> float4 aligned
    const float* base = inp + (size_t)b * (CC * HWSZ) + hw;

    int4 t = *reinterpret_cast<const int4*>(tgt + p);   // overlap with prologue

    // This thread's slot in stage 0 (stage s = +s*4096 bytes)
    unsigned int slot0 = (unsigned int)__cvta_generic_to_shared(&sbuf[tid]);

    // Prologue: fill all stages (channels 0..STAGES-1)
    #pragma unroll
    for (int s = 0; s < STAGES; ++s) {
        cp_async16(slot0 + s * 4096, base + (size_t)s * HWSZ);
        cp_commit();
    }

    float a0 = 0.f, a1 = 0.f, a2 = 0.f, a3 = 0.f;   // all-channel sums
    float s0 = 0.f, s1 = 0.f, s2 = 0.f, s3 = 0.f;   // target-group sums

    // Pre-consume channel 0 into registers; refill its slot with channel 4.
    cp_wait<STAGES - 1>();
    float4 v = sbuf[tid];
    cp_async16(slot0, base + (size_t)STAGES * HWSZ);
    cp_commit();

    #pragma unroll 8
    for (int c = 0; c < CC - 1; ++c) {
        // v holds channel c. Stage of channel c+1: group issued 4 iters ago;
        // exactly 3 younger groups in flight -> wait<3> guarantees it.
        cp_wait<STAGES - 1>();
        int slotn = (c + 1) & (STAGES - 1);          // compile-time under unroll
        float4 vn = sbuf[slotn * 256 + tid];         // LDS hides under compute(c)
        int g = sgid[c];

        float e0 = __expf(v.x), e1 = __expf(v.y);
        float e2 = __expf(v.z), e3 = __expf(v.w);
        a0 += e0; a1 += e1; a2 += e2; a3 += e3;
        if (g == t.x) s0 += e0;
        if (g == t.y) s1 += e1;
        if (g == t.z) s2 += e2;
        if (g == t.w) s3 += e3;

        int nc = c + 1 + STAGES;
        if (nc < CC)
            cp_async16(slot0 + slotn * 4096, base + (size_t)nc * HWSZ);
        cp_commit();                                 // empty tail groups are fine
        v = vn;
    }
    {   // channel 63
        int g = sgid[CC - 1];
        float e0 = __expf(v.x), e1 = __expf(v.y);
        float e2 = __expf(v.z), e3 = __expf(v.w);
        a0 += e0; a1 += e1; a2 += e2; a3 += e3;
        if (g == t.x) s0 += e0;
        if (g == t.y) s1 += e1;
        if (g == t.z) s2 += e2;
        if (g == t.w) s3 += e3;
    }

    // Targets outside [0, N_ORI) (incl. ignore=255) never matched -> s stays 0.
    bool v0 = (unsigned)t.x < N_ORI;
    bool v1 = (unsigned)t.y < N_ORI;
    bool v2 = (unsigned)t.z < N_ORI;
    bool v3 = (unsigned)t.w < N_ORI;

    float lsum = 0.0f;
    int   lcnt = 0;
    // -(log(s_t) - log(s_all)) = log(s_all) - log(s_t)
    if (v0) { lsum += __logf(a0) - __logf(s0); lcnt++; }
    if (v1) { lsum += __logf(a1) - __logf(s1); lcnt++; }
    if (v2) { lsum += __logf(a2) - __logf(s2); lcnt++; }
    if (v3) { lsum += __logf(a3) - __logf(s3); lcnt++; }

    // Warp reduce
    #pragma unroll
    for (int o = 16; o > 0; o >>= 1) {
        lsum += __shfl_down_sync(0xFFFFFFFFu, lsum, o);
        lcnt += __shfl_down_sync(0xFFFFFFFFu, lcnt, o);
    }

    __shared__ float wsum[8];
    __shared__ int   wcnt[8];
    int wid = tid >> 5;
    int lid = tid & 31;
    if (lid == 0) { wsum[wid] = lsum; wcnt[wid] = lcnt; }
    __syncthreads();

    __shared__ bool s_last;
    if (tid == 0) {
        float bs = 0.f; int bc = 0;
        #pragma unroll
        for (int w = 0; w < 8; ++w) { bs += wsum[w]; bc += wcnt[w]; }
        atomicAdd(&g_sum, (double)bs);
        atomicAdd(&g_cnt, (unsigned long long)bc);
        __threadfence();
        unsigned int ticket = atomicAdd(&g_ticket, 1u);
        s_last = (ticket == NBLOCKS - 1);
    }
    __syncthreads();

    if (s_last && tid == 0) {
        double sum = atomicAdd(&g_sum, 0.0);                    // acquire-read
        unsigned long long n = atomicAdd(&g_cnt, 0ull);
        if (n < 1ull) n = 1ull;
        out[0] = (float)(sum / (double)n);
        // Reset scratch for the next graph replay (deterministic).
        g_sum = 0.0;
        g_cnt = 0ull;
        __threadfence();
        g_ticket = 0u;
    }
}

extern "C" void kernel_launch(void* const* d_in, const int* in_sizes, int n_in,
                              void* d_out, int out_size) {
    const float* inp = (const float*)d_in[0];
    const int*   tgt = (const int*)d_in[1];
    const int*   gid = (const int*)d_in[2];
    float*       out = (float*)d_out;

    uce_kernel<<<NBLOCKS, 256>>>(inp, tgt, gid, out);
}

// round 15
// speedup vs baseline: 1.0617x; 1.0102x over previous
#include <cuda_runtime.h>

#define BB 4
#define CC 64
#define HH 512
#define WW 512
#define HWSZ (HH * WW)            // 262144
#define NPIX (BB * HWSZ)          // 1048576
#define NQUAD (NPIX / 4)          // 262144
#define NTHR 128
#define NBLOCKS (NQUAD / (2 * NTHR))   // 1024, 2 quads per thread
#define N_ORI 20
#define STAGES 4                  // 32B/thread per stage (two 16B halves), 16 KB ring
#define IGN 255

// Scratch (allocation-free per harness rules). Statically zeroed for first
// run; the last block of each run resets them, keeping graph replays
// deterministic.
__device__ double g_sum = 0.0;
__device__ unsigned long long g_cnt = 0ull;
__device__ unsigned int g_ticket = 0u;

__device__ __forceinline__ void cp_async16(unsigned int saddr, const void* gptr) {
    asm volatile("cp.async.cg.shared.global [%0], [%1], 16;\n"
                 :: "r"(saddr), "l"(gptr) : "memory");
}
__device__ __forceinline__ void cp_commit() {
    asm volatile("cp.async.commit_group;\n" ::: "memory");
}
template <int N>
__device__ __forceinline__ void cp_wait() {
    asm volatile("cp.async.wait_group %0;\n" :: "n"(N) : "memory");
}

__global__ __launch_bounds__(NTHR, 8) void uce_kernel(
    const float* __restrict__ inp,   // [B, C, H, W] f32
    const int* __restrict__ tgt,     // [B, H, W] int32
    const int* __restrict__ gid,     // [C] int32
    float* __restrict__ out)
{
    // Stage s (4 KB): half A = [s*256 .. +127], half B = [s*256+128 .. +255]
    __shared__ __align__(16) float4 sbuf[STAGES * 2 * NTHR];
    __shared__ int sgid[CC];

    int tid = threadIdx.x;
    if (tid < CC) sgid[tid] = gid[tid];
    __syncthreads();

    // Two quads per thread: qA and qB = qA + 128 (same batch image b)
    int qA = blockIdx.x * (2 * NTHR) + tid;
    int pA = qA << 2;
    int pB = pA + (NTHR << 2);               // +512 pixels
    int b  = pA >> 18;                       // block never crosses b boundary
    int hw = pA & (HWSZ - 1);
    const float* baseA = inp + (size_t)b * (CC * HWSZ) + hw;   // baseB = +512

    int4 tA = *reinterpret_cast<const int4*>(tgt + pA);
    int4 tB = *reinterpret_cast<const int4*>(tgt + pB);

    unsigned int slotA = (unsigned int)__cvta_generic_to_shared(&sbuf[tid]);
    unsigned int slotB = slotA + NTHR * 16;  // +2 KB

    // Prologue: fill all stages (channels 0..STAGES-1), one group per stage
    #pragma unroll
    for (int s = 0; s < STAGES; ++s) {
        const float* g = baseA + (size_t)s * HWSZ;
        cp_async16(slotA + s * 4096, g);
        cp_async16(slotB + s * 4096, g + 512);
        cp_commit();
    }

    float a0 = 0.f, a1 = 0.f, a2 = 0.f, a3 = 0.f;   // quad A all-channel sums
    float a4 = 0.f, a5 = 0.f, a6 = 0.f, a7 = 0.f;   // quad B
    float s0 = 0.f, s1 = 0.f, s2 = 0.f, s3 = 0.f;   // quad A target-group sums
    float s4 = 0.f, s5 = 0.f, s6 = 0.f, s7 = 0.f;   // quad B

    #pragma unroll 8
    for (int c = 0; c < CC; ++c) {
        cp_wait<STAGES - 1>();                       // oldest stage (channel c) ready
        int slot = (c & (STAGES - 1));               // compile-time under unroll 8
        float4 vA = sbuf[slot * 256 + tid];
        float4 vB = sbuf[slot * 256 + NTHR + tid];
        int g = sgid[c];

        float e0 = __expf(vA.x), e1 = __expf(vA.y);
        float e2 = __expf(vA.z), e3 = __expf(vA.w);
        float e4 = __expf(vB.x), e5 = __expf(vB.y);
        float e6 = __expf(vB.z), e7 = __expf(vB.w);
        a0 += e0; a1 += e1; a2 += e2; a3 += e3;
        a4 += e4; a5 += e5; a6 += e6; a7 += e7;
        if (g == tA.x) s0 += e0;
        if (g == tA.y) s1 += e1;
        if (g == tA.z) s2 += e2;
        if (g == tA.w) s3 += e3;
        if (g == tB.x) s4 += e4;
        if (g == tB.y) s5 += e5;
        if (g == tB.z) s6 += e6;
        if (g == tB.w) s7 += e7;

        int nc = c + STAGES;
        if (nc < CC) {
            const float* gp = baseA + (size_t)nc * HWSZ;
            cp_async16(slotA + slot * 4096, gp);
            cp_async16(slotB + slot * 4096, gp + 512);
        }
        cp_commit();                                 // empty tail groups are fine
    }

    // Targets outside [0, N_ORI) (incl. ignore=255) never matched -> s stays 0.
    float lsum = 0.0f;
    int   lcnt = 0;
    if ((unsigned)tA.x < N_ORI) { lsum += __logf(a0) - __logf(s0); lcnt++; }
    if ((unsigned)tA.y < N_ORI) { lsum += __logf(a1) - __logf(s1); lcnt++; }
    if ((unsigned)tA.z < N_ORI) { lsum += __logf(a2) - __logf(s2); lcnt++; }
    if ((unsigned)tA.w < N_ORI) { lsum += __logf(a3) - __logf(s3); lcnt++; }
    if ((unsigned)tB.x < N_ORI) { lsum += __logf(a4) - __logf(s4); lcnt++; }
    if ((unsigned)tB.y < N_ORI) { lsum += __logf(a5) - __logf(s5); lcnt++; }
    if ((unsigned)tB.z < N_ORI) { lsum += __logf(a6) - __logf(s6); lcnt++; }
    if ((unsigned)tB.w < N_ORI) { lsum += __logf(a7) - __logf(s7); lcnt++; }

    // Warp reduce
    #pragma unroll
    for (int o = 16; o > 0; o >>= 1) {
        lsum += __shfl_down_sync(0xFFFFFFFFu, lsum, o);
        lcnt += __shfl_down_sync(0xFFFFFFFFu, lcnt, o);
    }

    __shared__ float wsum[4];
    __shared__ int   wcnt[4];
    int wid = tid >> 5;
    int lid = tid & 31;
    if (lid == 0) { wsum[wid] = lsum; wcnt[wid] = lcnt; }
    __syncthreads();

    __shared__ bool s_last;
    if (tid == 0) {
        float bs = 0.f; int bc = 0;
        #pragma unroll
        for (int w = 0; w < 4; ++w) { bs += wsum[w]; bc += wcnt[w]; }
        atomicAdd(&g_sum, (double)bs);
        atomicAdd(&g_cnt, (unsigned long long)bc);
        __threadfence();
        unsigned int ticket = atomicAdd(&g_ticket, 1u);
        s_last = (ticket == NBLOCKS - 1);
    }
    __syncthreads();

    if (s_last && tid == 0) {
        double sum = atomicAdd(&g_sum, 0.0);                    // acquire-read
        unsigned long long n = atomicAdd(&g_cnt, 0ull);
        if (n < 1ull) n = 1ull;
        out[0] = (float)(sum / (double)n);
        // Reset scratch for the next graph replay (deterministic).
        g_sum = 0.0;
        g_cnt = 0ull;
        __threadfence();
        g_ticket = 0u;
    }
}

extern "C" void kernel_launch(void* const* d_in, const int* in_sizes, int n_in,
                              void* d_out, int out_size) {
    const float* inp = (const float*)d_in[0];
    const int*   tgt = (const int*)d_in[1];
    const int*   gid = (const int*)d_in[2];
    float*       out = (float*)d_out;

    uce_kernel<<<NBLOCKS, NTHR>>>(inp, tgt, gid, out);
}

// round 17
// speedup vs baseline: 1.0935x; 1.0300x over previous
#include <cuda_runtime.h>

#define BB 4
#define CC 64
#define HH 512
#define WW 512
#define HWSZ (HH * WW)            // 262144
#define NPIX (BB * HWSZ)          // 1048576
#define NQUAD (NPIX / 4)          // 262144
#define NTHR 128
#define TQUADS 128                // quads per tile (1 per thread)
#define NTILES (NQUAD / TQUADS)   // 2048
#define NCTAS (148 * 7)           // 1036 persistent CTAs, exactly 7/SM
#define N_ORI 20
#define STAGES 4                  // 16B/thread per stage, 8 KB ring
#define IGN 255

// Scratch (allocation-free per harness rules). Statically zeroed for first
// run; the finalizing CTA resets everything, keeping graph replays correct.
__device__ double g_sum = 0.0;
__device__ unsigned long long g_cnt = 0ull;
__device__ unsigned int g_ticket = 0u;   // finalize rendezvous
__device__ unsigned int g_tile = 0u;     // work-stealing ticket

__device__ __forceinline__ void cp_async16(unsigned int saddr, const void* gptr) {
    asm volatile("cp.async.cg.shared.global [%0], [%1], 16;\n"
                 :: "r"(saddr), "l"(gptr) : "memory");
}
__device__ __forceinline__ void cp_commit() {
    asm volatile("cp.async.commit_group;\n" ::: "memory");
}
template <int N>
__device__ __forceinline__ void cp_wait() {
    asm volatile("cp.async.wait_group %0;\n" :: "n"(N) : "memory");
}

__global__ __launch_bounds__(NTHR, 7) void uce_kernel(
    const float* __restrict__ inp,   // [B, C, H, W] f32
    const int* __restrict__ tgt,     // [B, H, W] int32
    const int* __restrict__ gid,     // [C] int32
    float* __restrict__ out)
{
    __shared__ __align__(16) float4 sbuf[STAGES * NTHR];   // 8 KB ring
    __shared__ int sgid[CC];
    __shared__ int s_tile;

    int tid = threadIdx.x;
    if (tid < CC) sgid[tid] = gid[tid];
    if (tid == 0) s_tile = (int)atomicAdd(&g_tile, 1u);    // initial ticket (< NCTAS <= 2048, always valid)
    __syncthreads();

    int tile = s_tile;

    unsigned int slot0 = (unsigned int)__cvta_generic_to_shared(&sbuf[tid]);

    // tile t -> pixels [t*512, t*512+512); thread's first pixel:
    int p  = tile * (TQUADS * 4) + tid * 4;
    int b  = p >> 18;
    int hw = p & (HWSZ - 1);
    const float* base = inp + (size_t)b * (CC * HWSZ) + hw;
    int4 t4 = *reinterpret_cast<const int4*>(tgt + p);

    // Prologue: fill all stages (channels 0..3 of first tile)
    #pragma unroll
    for (int s = 0; s < STAGES; ++s) {
        cp_async16(slot0 + s * (NTHR * 16), base + (size_t)s * HWSZ);
        cp_commit();
    }

    float lsum = 0.0f;
    int   lcnt = 0;

    for (;;) {
        float a0 = 0.f, a1 = 0.f, a2 = 0.f, a3 = 0.f;
        float s0 = 0.f, s1 = 0.f, s2 = 0.f, s3 = 0.f;

        // Channels 0..59: consume (tile,c), refill slot with (tile,c+4)
        #pragma unroll 4
        for (int c = 0; c < CC - STAGES; ++c) {
            cp_wait<STAGES - 1>();
            int slot = c & (STAGES - 1);
            float4 v = sbuf[slot * NTHR + tid];
            int g = sgid[c];

            float e0 = __expf(v.x), e1 = __expf(v.y);
            float e2 = __expf(v.z), e3 = __expf(v.w);
            a0 += e0; a1 += e1; a2 += e2; a3 += e3;
            if (g == t4.x) s0 += e0;
            if (g == t4.y) s1 += e1;
            if (g == t4.z) s2 += e2;
            if (g == t4.w) s3 += e3;

            cp_async16(slot0 + slot * (NTHR * 16), base + (size_t)(c + STAGES) * HWSZ);
            cp_commit();
        }

        // Acquire next tile; broadcast; prefetch its targets.
        if (tid == 0) s_tile = (int)atomicAdd(&g_tile, 1u);
        __syncthreads();
        int ntile = s_tile;
        bool more = (ntile < NTILES);

        const float* nbase = base;
        int4 nt4 = t4;
        if (more) {
            int np  = ntile * (TQUADS * 4) + tid * 4;
            int nb  = np >> 18;
            int nhw = np & (HWSZ - 1);
            nbase = inp + (size_t)nb * (CC * HWSZ) + nhw;
            nt4 = *reinterpret_cast<const int4*>(tgt + np);   // hides under c=60..63
        }

        // Channels 60..63: consume (tile,c), refill slot with (ntile, c-60)
        #pragma unroll
        for (int c = CC - STAGES; c < CC; ++c) {
            cp_wait<STAGES - 1>();
            int slot = c & (STAGES - 1);
            float4 v = sbuf[slot * NTHR + tid];
            int g = sgid[c];

            float e0 = __expf(v.x), e1 = __expf(v.y);
            float e2 = __expf(v.z), e3 = __expf(v.w);
            a0 += e0; a1 += e1; a2 += e2; a3 += e3;
            if (g == t4.x) s0 += e0;
            if (g == t4.y) s1 += e1;
            if (g == t4.z) s2 += e2;
            if (g == t4.w) s3 += e3;

            if (more)
                cp_async16(slot0 + slot * (NTHR * 16), nbase + (size_t)(c - (CC - STAGES)) * HWSZ);
            cp_commit();
        }

        // Tile epilogue: targets outside [0,N_ORI) (incl. 255) never matched.
        if ((unsigned)t4.x < N_ORI) { lsum += __logf(a0) - __logf(s0); lcnt++; }
        if ((unsigned)t4.y < N_ORI) { lsum += __logf(a1) - __logf(s1); lcnt++; }
        if ((unsigned)t4.z < N_ORI) { lsum += __logf(a2) - __logf(s2); lcnt++; }
        if ((unsigned)t4.w < N_ORI) { lsum += __logf(a3) - __logf(s3); lcnt++; }

        if (!more) break;
        base = nbase;
        t4 = nt4;
    }

    // Warp reduce
    #pragma unroll
    for (int o = 16; o > 0; o >>= 1) {
        lsum += __shfl_down_sync(0xFFFFFFFFu, lsum, o);
        lcnt += __shfl_down_sync(0xFFFFFFFFu, lcnt, o);
    }

    __shared__ float wsum[4];
    __shared__ int   wcnt[4];
    int wid = tid >> 5;
    int lid = tid & 31;
    if (lid == 0) { wsum[wid] = lsum; wcnt[wid] = lcnt; }
    __syncthreads();

    __shared__ bool s_last;
    if (tid == 0) {
        float bs = 0.f; int bc = 0;
        #pragma unroll
        for (int w = 0; w < 4; ++w) { bs += wsum[w]; bc += wcnt[w]; }
        atomicAdd(&g_sum, (double)bs);
        atomicAdd(&g_cnt, (unsigned long long)bc);
        __threadfence();
        unsigned int ticket = atomicAdd(&g_ticket, 1u);
        s_last = (ticket == NCTAS - 1);
    }
    __syncthreads();

    if (s_last && tid == 0) {
        double sum = atomicAdd(&g_sum, 0.0);                    // acquire-read
        unsigned long long n = atomicAdd(&g_cnt, 0ull);
        if (n < 1ull) n = 1ull;
        out[0] = (float)(sum / (double)n);
        // Reset scratch for the next graph replay.
        g_sum = 0.0;
        g_cnt = 0ull;
        g_tile = 0u;
        __threadfence();
        g_ticket = 0u;
    }
}

extern "C" void kernel_launch(void* const* d_in, const int* in_sizes, int n_in,
                              void* d_out, int out_size) {
    const float* inp = (const float*)d_in[0];
    const int*   tgt = (const int*)d_in[1];
    const int*   gid = (const int*)d_in[2];
    float*       out = (float*)d_out;

    uce_kernel<<<NCTAS, NTHR>>>(inp, tgt, gid, out);
}